// round 12
// baseline (speedup 1.0000x reference)
#include <cuda_runtime.h>
#include <cuda_fp16.h>
#include <cstdint>

#define B_DIM 4
#define T_DIM 4096
#define E_DIM 2048
#define H_DIM 16
#define D_DIM 128
#define BT_DIM 16384

typedef __half f16;

// ---------------- scratch (device globals; no allocations allowed) ----------
__device__ f16 g_xh[(size_t)BT_DIM * E_DIM];
__device__ f16 g_Wh[4][(size_t)E_DIM * E_DIM];
__device__ f16 g_G[(size_t)B_DIM * E_DIM * E_DIM];   // Gram x^T x per batch (symmetric)
__device__ f16 g_Z[(size_t)B_DIM * E_DIM * E_DIM];   // Z = Wv G  [n][j]
__device__ f16 g_PB[(size_t)B_DIM * E_DIM * E_DIM];  // per-batch KV*Wo^T  [n][k]
__device__ f16 g_M[(size_t)B_DIM * E_DIM * E_DIM];   // Mt[b][n][j] = PB Wq
__device__ float g_fbias[B_DIM * E_DIM];
__device__ f16 g_KVth[64 * D_DIM * D_DIM];           // [bh][d][e], alpha+bias folded
__device__ float g_sx[B_DIM * E_DIM];                // column sums of x
__device__ float g_sxwk[B_DIM * E_DIM];              // Wk @ sx
__device__ float g_sxwv[B_DIM * E_DIM];              // Wv @ sx

// ---------------- helpers ----------------------------------------------------
__device__ __forceinline__ uint32_t smem_u32(const void* p) {
    uint32_t a;
    asm("{ .reg .u64 t; cvta.to.shared.u64 t, %1; cvt.u32.u64 %0, t; }" : "=r"(a) : "l"(p));
    return a;
}
__device__ __forceinline__ void cp_async16(uint32_t sdst, const void* gsrc) {
    asm volatile("cp.async.cg.shared.global [%0], [%1], 16;" :: "r"(sdst), "l"(gsrc) : "memory");
}
#define CP_COMMIT() asm volatile("cp.async.commit_group;" ::: "memory")
#define CP_WAIT1()  asm volatile("cp.async.wait_group 1;" ::: "memory")

__device__ __forceinline__ void ldsm4(uint32_t* r, uint32_t a) {
    asm volatile("ldmatrix.sync.aligned.m8n8.x4.shared.b16 {%0,%1,%2,%3}, [%4];"
                 : "=r"(r[0]), "=r"(r[1]), "=r"(r[2]), "=r"(r[3]) : "r"(a));
}
__device__ __forceinline__ void ldsm4t(uint32_t* r, uint32_t a) {
    asm volatile("ldmatrix.sync.aligned.m8n8.x4.trans.shared.b16 {%0,%1,%2,%3}, [%4];"
                 : "=r"(r[0]), "=r"(r[1]), "=r"(r[2]), "=r"(r[3]) : "r"(a));
}
__device__ __forceinline__ void mma_f16(float* c, const uint32_t* a, const uint32_t* b) {
    asm volatile(
        "mma.sync.aligned.m16n8k16.row.col.f32.f16.f16.f32 "
        "{%0,%1,%2,%3}, {%4,%5,%6,%7}, {%8,%9}, {%0,%1,%2,%3};"
        : "+f"(c[0]), "+f"(c[1]), "+f"(c[2]), "+f"(c[3])
        : "r"(a[0]), "r"(a[1]), "r"(a[2]), "r"(a[3]), "r"(b[0]), "r"(b[1]));
}

// 128B-row tile loader (64 f16/row), swizzle chunk c^(r&7)
__device__ __forceinline__ void load_rows64(uint32_t sdst, const f16* __restrict__ g,
                                            int row0, int col0, int ld, int iters) {
    const int t = threadIdx.x;
    #pragma unroll 8
    for (int i = 0; i < iters; i++) {
        int idx = t + i * 256;
        int r = idx >> 3, c = idx & 7;
        const f16* src = g + (size_t)(row0 + r) * ld + col0 + c * 8;
        cp_async16(sdst + r * 128 + ((c ^ (r & 7)) << 4), src);
    }
}
// 256B-row tile: 64 rows x 128 f16 (16 chunks)
__device__ __forceinline__ void load_tile256B(uint32_t sdst, const f16* __restrict__ g,
                                              int row0, int col0, int ld) {
    const int t = threadIdx.x;
    #pragma unroll
    for (int i = 0; i < 4; i++) {
        int idx = t + i * 256;
        int r = idx >> 4, cc = idx & 15;
        const f16* src = g + (size_t)(row0 + r) * ld + col0 + cc * 8;
        cp_async16(sdst + r * 256 + ((cc ^ (r & 7)) << 4), src);
    }
}
// 512B-row tile: 64 rows x 256 f16 (32 chunks)
__device__ __forceinline__ void load_tile512B(uint32_t sdst, const f16* __restrict__ g,
                                              int row0, int col0, int ld) {
    const int t = threadIdx.x;
    #pragma unroll
    for (int i = 0; i < 8; i++) {
        int idx = t + i * 256;
        int r = idx >> 5, cc = idx & 31;
        const f16* src = g + (size_t)(row0 + r) * ld + col0 + cc * 8;
        cp_async16(sdst + r * 512 + ((cc ^ (r & 7)) << 4), src);
    }
}

// ---------------- big GEMM core: CTA 128x256, warp 64x64, BK=128, 2 stages ---
#define PG_A0 0
#define PG_A1 16384
#define PG_B0 32768
#define PG_B1 65536
#define PG_STAGE 98304
#define PG_SMEM  (2 * PG_STAGE)

__device__ __forceinline__ void gemm_128x256_core(
    const f16* __restrict__ Ah, const f16* __restrict__ Bh,
    const float* __restrict__ bias, bool out_f32,
    float* __restrict__ Cf, f16* __restrict__ C1)
{
    extern __shared__ __align__(1024) char smdyn[];
    const uint32_t sbase = smem_u32(smdyn);
    const int tid = threadIdx.x;
    const int wid = tid >> 5, lane = tid & 31;
    const int wm = (wid & 1) * 64;
    const int wn = (wid >> 1) * 64;
    const int row0 = blockIdx.y * 128;
    const int n0 = blockIdx.x * 256;

    uint32_t abase[4];
    #pragma unroll
    for (int mi = 0; mi < 4; mi++) {
        int r = wm + mi * 16 + (lane & 15);
        int hi = lane >> 4;
        abase[mi] = r * 128 + ((hi ^ (r & 7)) << 4);
    }
    uint32_t bbase[4];
    #pragma unroll
    for (int p = 0; p < 4; p++) {
        int g2 = lane >> 3;
        int r = wn + p * 16 + ((g2 >> 1) << 3) + (lane & 7);
        bbase[p] = r * 128 + (((g2 & 1) ^ (r & 7)) << 4);
    }

    float acc[4][8][4];
    #pragma unroll
    for (int mi = 0; mi < 4; mi++)
        #pragma unroll
        for (int ni = 0; ni < 8; ni++)
            #pragma unroll
            for (int q = 0; q < 4; q++) acc[mi][ni][q] = 0.0f;

    #pragma unroll
    for (int i = 0; i < 2; i++) {
        uint32_t sb = sbase + i * PG_STAGE;
        int k0 = i * 128;
        load_rows64(sb + PG_A0, Ah, row0, k0,      E_DIM, 4);
        load_rows64(sb + PG_A1, Ah, row0, k0 + 64, E_DIM, 4);
        load_rows64(sb + PG_B0, Bh, n0,   k0,      E_DIM, 8);
        load_rows64(sb + PG_B1, Bh, n0,   k0 + 64, E_DIM, 8);
        CP_COMMIT();
    }

    const int NC = E_DIM / 128;
    for (int c = 0; c < NC; c++) {
        CP_WAIT1();
        __syncthreads();
        const uint32_t sb = sbase + (c & 1) * PG_STAGE;
        #pragma unroll
        for (int ks = 0; ks < 8; ks++) {
            const uint32_t asub = sb + ((ks & 4) ? PG_A1 : PG_A0);
            const uint32_t bsub = sb + ((ks & 4) ? PG_B1 : PG_B0);
            const uint32_t kx = (ks & 3) << 5;
            uint32_t ah[4][4], bh[8][2];
            #pragma unroll
            for (int mi = 0; mi < 4; mi++)
                ldsm4(ah[mi], asub + (abase[mi] ^ kx));
            #pragma unroll
            for (int p = 0; p < 4; p++) {
                uint32_t t4[4];
                ldsm4(t4, bsub + (bbase[p] ^ kx));
                bh[2 * p][0] = t4[0]; bh[2 * p][1] = t4[1];
                bh[2 * p + 1][0] = t4[2]; bh[2 * p + 1][1] = t4[3];
            }
            #pragma unroll
            for (int mi = 0; mi < 4; mi++)
                #pragma unroll
                for (int ni = 0; ni < 8; ni++)
                    mma_f16(acc[mi][ni], ah[mi], bh[ni]);
        }
        __syncthreads();
        if (c + 2 < NC) {
            uint32_t sb2 = sbase + (c & 1) * PG_STAGE;
            int k0 = (c + 2) * 128;
            load_rows64(sb2 + PG_A0, Ah, row0, k0,      E_DIM, 4);
            load_rows64(sb2 + PG_A1, Ah, row0, k0 + 64, E_DIM, 4);
            load_rows64(sb2 + PG_B0, Bh, n0,   k0,      E_DIM, 8);
            load_rows64(sb2 + PG_B1, Bh, n0,   k0 + 64, E_DIM, 8);
        }
        CP_COMMIT();
    }

    const int lg = lane >> 2;
    const int lc2 = (lane & 3) * 2;
    #pragma unroll
    for (int mi = 0; mi < 4; mi++) {
        #pragma unroll
        for (int half = 0; half < 2; half++) {
            int row = row0 + wm + mi * 16 + lg + half * 8;
            #pragma unroll
            for (int ni = 0; ni < 8; ni++) {
                int col = n0 + wn + ni * 8 + lc2;
                float v0 = acc[mi][ni][half * 2 + 0] + bias[col];
                float v1 = acc[mi][ni][half * 2 + 1] + bias[col + 1];
                if (out_f32) {
                    *reinterpret_cast<float2*>(Cf + (size_t)row * E_DIM + col) = make_float2(v0, v1);
                } else {
                    *reinterpret_cast<uint32_t*>(C1 + (size_t)row * E_DIM + col) =
                        (uint32_t)__half_as_ushort(__float2half_rn(v0)) |
                        ((uint32_t)__half_as_ushort(__float2half_rn(v1)) << 16);
                }
            }
        }
    }
}

// final output: OUT = x @ Mt[b]^T + fbias[b]   (grid (8, 128))
__global__ __launch_bounds__(256, 1) void k_out(float* __restrict__ out)
{
    const int b = blockIdx.y >> 5;
    gemm_128x256_core(g_xh, g_M + (size_t)b * E_DIM * E_DIM,
                      g_fbias + b * E_DIM, true, out, nullptr);
}

// ---------------- A@B with B stored [k][j] (trans-loaded): C[m][j] -----------
// grid (j/256, m/128, z). Used for Z = Wv G  and  M = PB Wq.
__global__ __launch_bounds__(256, 1) void k_ABt(
    const f16* __restrict__ Abase, size_t Astride,
    const f16* __restrict__ Btbase, size_t Btstride,
    f16* __restrict__ Cbase, size_t Cstride)
{
    extern __shared__ __align__(1024) char smdyn[];
    const uint32_t sbase = smem_u32(smdyn);
    const int tid = threadIdx.x;
    const int wid = tid >> 5, lane = tid & 31;
    const int wm = (wid & 1) * 64;
    const int wn = (wid >> 1) * 64;
    const int z = blockIdx.z;
    const int row0 = blockIdx.y * 128;
    const int j0 = blockIdx.x * 256;
    const f16* Ah = Abase + (size_t)z * Astride;
    const f16* Bt = Btbase + (size_t)z * Btstride;
    f16* Cout = Cbase + (size_t)z * Cstride;
    const int q = lane >> 3;

    uint32_t abase[4];
    #pragma unroll
    for (int mi = 0; mi < 4; mi++) {
        int r = wm + mi * 16 + (lane & 15);
        int hi = lane >> 4;
        abase[mi] = r * 128 + ((hi ^ (r & 7)) << 4);
    }
    uint32_t btbase[4];
    #pragma unroll
    for (int p = 0; p < 4; p++) {
        int r0 = ((q & 1) << 3) + (lane & 7);
        int cc = ((wn + p * 16) >> 3) + (q >> 1);
        btbase[p] = r0 * 512 + ((cc ^ (r0 & 7)) << 4);
    }

    float acc[4][8][4];
    #pragma unroll
    for (int mi = 0; mi < 4; mi++)
        #pragma unroll
        for (int ni = 0; ni < 8; ni++)
            #pragma unroll
            for (int qq = 0; qq < 4; qq++) acc[mi][ni][qq] = 0.0f;

    #pragma unroll
    for (int i = 0; i < 2; i++) {
        uint32_t sb = sbase + i * PG_STAGE;
        int k0 = i * 128;
        load_rows64(sb + PG_A0, Ah, row0, k0,      E_DIM, 4);
        load_rows64(sb + PG_A1, Ah, row0, k0 + 64, E_DIM, 4);
        load_tile512B(sb + PG_B0, Bt, k0,      j0, E_DIM);
        load_tile512B(sb + PG_B1, Bt, k0 + 64, j0, E_DIM);
        CP_COMMIT();
    }

    const int NC = E_DIM / 128;
    for (int c = 0; c < NC; c++) {
        CP_WAIT1();
        __syncthreads();
        const uint32_t sb = sbase + (c & 1) * PG_STAGE;
        #pragma unroll
        for (int ks = 0; ks < 8; ks++) {
            const uint32_t asub = sb + ((ks & 4) ? PG_A1 : PG_A0);
            const uint32_t bsub = sb + ((ks & 4) ? PG_B1 : PG_B0);
            const uint32_t kx = (ks & 3) << 5;
            const uint32_t kofs = (uint32_t)(ks & 3) * 8192;
            uint32_t ah[4][4], bh[8][2];
            #pragma unroll
            for (int mi = 0; mi < 4; mi++)
                ldsm4(ah[mi], asub + (abase[mi] ^ kx));
            #pragma unroll
            for (int p = 0; p < 4; p++) {
                uint32_t t4[4];
                ldsm4t(t4, bsub + btbase[p] + kofs);
                bh[2 * p][0] = t4[0]; bh[2 * p][1] = t4[1];
                bh[2 * p + 1][0] = t4[2]; bh[2 * p + 1][1] = t4[3];
            }
            #pragma unroll
            for (int mi = 0; mi < 4; mi++)
                #pragma unroll
                for (int ni = 0; ni < 8; ni++)
                    mma_f16(acc[mi][ni], ah[mi], bh[ni]);
        }
        __syncthreads();
        if (c + 2 < NC) {
            uint32_t sb2 = sbase + (c & 1) * PG_STAGE;
            int k0 = (c + 2) * 128;
            load_rows64(sb2 + PG_A0, Ah, row0, k0,      E_DIM, 4);
            load_rows64(sb2 + PG_A1, Ah, row0, k0 + 64, E_DIM, 4);
            load_tile512B(sb2 + PG_B0, Bt, k0,      j0, E_DIM);
            load_tile512B(sb2 + PG_B1, Bt, k0 + 64, j0, E_DIM);
        }
        CP_COMMIT();
    }

    const int lg = lane >> 2;
    const int lc2 = (lane & 3) * 2;
    #pragma unroll
    for (int mi = 0; mi < 4; mi++) {
        #pragma unroll
        for (int half = 0; half < 2; half++) {
            int row = row0 + wm + mi * 16 + lg + half * 8;
            #pragma unroll
            for (int ni = 0; ni < 8; ni++) {
                int col = j0 + wn + ni * 8 + lc2;
                *reinterpret_cast<uint32_t*>(Cout + (size_t)row * E_DIM + col) =
                    (uint32_t)__half_as_ushort(__float2half_rn(acc[mi][ni][half * 2 + 0])) |
                    ((uint32_t)__half_as_ushort(__float2half_rn(acc[mi][ni][half * 2 + 1])) << 16);
            }
        }
    }
}

// ---------------- Gram: G[b][i][j] = sum_t x[b,t,i] x[b,t,j] -----------------
// Both operands trans-loaded. grid (j/256=8, i/128=16, b). BK=64, 2 stages (96KB).
#define GR_A 0
#define GR_B 16384
#define GR_STAGE 49152
#define GR_SMEM  (2 * GR_STAGE)

__global__ __launch_bounds__(256, 1) void k_gram()
{
    extern __shared__ __align__(1024) char smdyn[];
    const uint32_t sbase = smem_u32(smdyn);
    const int tid = threadIdx.x;
    const int wid = tid >> 5, lane = tid & 31;
    const int wm = (wid & 1) * 64;
    const int wn = (wid >> 1) * 64;
    const int b = blockIdx.z;
    const int i0 = blockIdx.y * 128;
    const int j0 = blockIdx.x * 256;
    const int bt0 = b * T_DIM;
    const int q = lane >> 3;
    f16* Gout = g_G + (size_t)b * E_DIM * E_DIM;

    // A trans frags (256B rows, kv_mma-validated)
    uint32_t abase[4];
    #pragma unroll
    for (int mi = 0; mi < 4; mi++) {
        int r0 = ((q & 2) << 2) + (lane & 7);
        int cc = ((wm + mi * 16) >> 3) + (q & 1);
        abase[mi] = r0 * 256 + ((cc ^ (r0 & 7)) << 4);
    }
    // B trans frags (512B rows, mbuild-validated)
    uint32_t btbase[4];
    #pragma unroll
    for (int p = 0; p < 4; p++) {
        int r0 = ((q & 1) << 3) + (lane & 7);
        int cc = ((wn + p * 16) >> 3) + (q >> 1);
        btbase[p] = r0 * 512 + ((cc ^ (r0 & 7)) << 4);
    }

    float acc[4][8][4];
    #pragma unroll
    for (int mi = 0; mi < 4; mi++)
        #pragma unroll
        for (int ni = 0; ni < 8; ni++)
            #pragma unroll
            for (int qq = 0; qq < 4; qq++) acc[mi][ni][qq] = 0.0f;

    #pragma unroll
    for (int i = 0; i < 2; i++) {
        uint32_t sb = sbase + i * GR_STAGE;
        load_tile256B(sb + GR_A, g_xh, bt0 + i * 64, i0, E_DIM);
        load_tile512B(sb + GR_B, g_xh, bt0 + i * 64, j0, E_DIM);
        CP_COMMIT();
    }

    const int NC = T_DIM / 64;   // 64
    for (int c = 0; c < NC; c++) {
        CP_WAIT1();
        __syncthreads();
        const uint32_t sb = sbase + (c & 1) * GR_STAGE;
        #pragma unroll
        for (int ks = 0; ks < 4; ks++) {
            uint32_t ah[4][4], bh[8][2];
            #pragma unroll
            for (int mi = 0; mi < 4; mi++)
                ldsm4t(ah[mi], sb + GR_A + abase[mi] + ks * 4096);
            #pragma unroll
            for (int p = 0; p < 4; p++) {
                uint32_t t4[4];
                ldsm4t(t4, sb + GR_B + btbase[p] + ks * 8192);
                bh[2 * p][0] = t4[0]; bh[2 * p][1] = t4[1];
                bh[2 * p + 1][0] = t4[2]; bh[2 * p + 1][1] = t4[3];
            }
            #pragma unroll
            for (int mi = 0; mi < 4; mi++)
                #pragma unroll
                for (int ni = 0; ni < 8; ni++)
                    mma_f16(acc[mi][ni], ah[mi], bh[ni]);
        }
        __syncthreads();
        if (c + 2 < NC) {
            uint32_t sb2 = sbase + (c & 1) * GR_STAGE;
            load_tile256B(sb2 + GR_A, g_xh, bt0 + (c + 2) * 64, i0, E_DIM);
            load_tile512B(sb2 + GR_B, g_xh, bt0 + (c + 2) * 64, j0, E_DIM);
        }
        CP_COMMIT();
    }

    const int lg = lane >> 2;
    const int lc2 = (lane & 3) * 2;
    #pragma unroll
    for (int mi = 0; mi < 4; mi++) {
        #pragma unroll
        for (int half = 0; half < 2; half++) {
            int row = i0 + wm + mi * 16 + lg + half * 8;
            #pragma unroll
            for (int ni = 0; ni < 8; ni++) {
                int col = j0 + wn + ni * 8 + lc2;
                *reinterpret_cast<uint32_t*>(Gout + (size_t)row * E_DIM + col) =
                    (uint32_t)__half_as_ushort(__float2half_rn(acc[mi][ni][half * 2 + 0])) |
                    ((uint32_t)__half_as_ushort(__float2half_rn(acc[mi][ni][half * 2 + 1])) << 16);
            }
        }
    }
}

// ---------------- KVh: KV_h[d][e] = Wk_h @ Z_h^T + rank-1 bias terms ---------
// CTA 128x128, K=2048, 8 warps of 64x32. grid (64) = bh.
#define KH_A0 0
#define KH_A1 16384
#define KH_B0 32768
#define KH_B1 49152
#define KH_STAGE 65536
#define KH_SMEM  (2 * KH_STAGE)

__global__ __launch_bounds__(256, 1) void k_kvh(
    const float* __restrict__ bk, const float* __restrict__ bv)
{
    const float alpha = 0.08838834764831845f;
    const int bh = blockIdx.x;
    const int b = bh >> 4;
    const int h = bh & 15;
    const int colh = h * 128;
    const f16* Ah = g_Wh[1];                        // Wk, rows colh+d
    const f16* Bh = g_Z + (size_t)b * E_DIM * E_DIM; // rows colh+e

    extern __shared__ __align__(1024) char smdyn[];
    const uint32_t sbase = smem_u32(smdyn);
    const int tid = threadIdx.x;
    const int wid = tid >> 5, lane = tid & 31;
    const int wm = (wid & 1) * 64;
    const int wn = (wid >> 1) * 32;

    uint32_t abase[4];
    #pragma unroll
    for (int mi = 0; mi < 4; mi++) {
        int r = wm + mi * 16 + (lane & 15);
        int hi = lane >> 4;
        abase[mi] = r * 128 + ((hi ^ (r & 7)) << 4);
    }
    uint32_t bbase[2];
    #pragma unroll
    for (int p = 0; p < 2; p++) {
        int g2 = lane >> 3;
        int r = wn + p * 16 + ((g2 >> 1) << 3) + (lane & 7);
        bbase[p] = r * 128 + (((g2 & 1) ^ (r & 7)) << 4);
    }

    float acc[4][4][4];
    #pragma unroll
    for (int mi = 0; mi < 4; mi++)
        #pragma unroll
        for (int ni = 0; ni < 4; ni++)
            #pragma unroll
            for (int qq = 0; qq < 4; qq++) acc[mi][ni][qq] = 0.0f;

    #pragma unroll
    for (int i = 0; i < 2; i++) {
        uint32_t sb = sbase + i * KH_STAGE;
        int k0 = i * 128;
        load_rows64(sb + KH_A0, Ah, colh, k0,      E_DIM, 4);
        load_rows64(sb + KH_A1, Ah, colh, k0 + 64, E_DIM, 4);
        load_rows64(sb + KH_B0, Bh, colh, k0,      E_DIM, 4);
        load_rows64(sb + KH_B1, Bh, colh, k0 + 64, E_DIM, 4);
        CP_COMMIT();
    }

    const int NC = E_DIM / 128;   // 16
    for (int c = 0; c < NC; c++) {
        CP_WAIT1();
        __syncthreads();
        const uint32_t sb = sbase + (c & 1) * KH_STAGE;
        #pragma unroll
        for (int ks = 0; ks < 8; ks++) {
            const uint32_t asub = sb + ((ks & 4) ? KH_A1 : KH_A0);
            const uint32_t bsub = sb + ((ks & 4) ? KH_B1 : KH_B0);
            const uint32_t kx = (ks & 3) << 5;
            uint32_t ah[4][4], bh2[4][2];
            #pragma unroll
            for (int mi = 0; mi < 4; mi++)
                ldsm4(ah[mi], asub + (abase[mi] ^ kx));
            #pragma unroll
            for (int p = 0; p < 2; p++) {
                uint32_t t4[4];
                ldsm4(t4, bsub + (bbase[p] ^ kx));
                bh2[2 * p][0] = t4[0]; bh2[2 * p][1] = t4[1];
                bh2[2 * p + 1][0] = t4[2]; bh2[2 * p + 1][1] = t4[3];
            }
            #pragma unroll
            for (int mi = 0; mi < 4; mi++)
                #pragma unroll
                for (int ni = 0; ni < 4; ni++)
                    mma_f16(acc[mi][ni], ah[mi], bh2[ni]);
        }
        __syncthreads();
        if (c + 2 < NC) {
            uint32_t sb2 = sbase + (c & 1) * KH_STAGE;
            int k0 = (c + 2) * 128;
            load_rows64(sb2 + KH_A0, Ah, colh, k0,      E_DIM, 4);
            load_rows64(sb2 + KH_A1, Ah, colh, k0 + 64, E_DIM, 4);
            load_rows64(sb2 + KH_B0, Bh, colh, k0,      E_DIM, 4);
            load_rows64(sb2 + KH_B1, Bh, colh, k0 + 64, E_DIM, 4);
        }
        CP_COMMIT();
    }

    f16* Cg = g_KVth + ((size_t)bh << 14);
    const int lg = lane >> 2;
    const int lc2 = (lane & 3) * 2;
    #pragma unroll
    for (int mi = 0; mi < 4; mi++)
        #pragma unroll
        for (int half = 0; half < 2; half++) {
            int d = wm + mi * 16 + lg + half * 8;
            float bkd = bk[colh + d];
            float skd = g_sxwk[b * E_DIM + colh + d];
            #pragma unroll
            for (int ni = 0; ni < 4; ni++) {
                int e = wn + ni * 8 + lc2;
                float bv0 = bv[colh + e],     bv1 = bv[colh + e + 1];
                float sv0 = g_sxwv[b * E_DIM + colh + e];
                float sv1 = g_sxwv[b * E_DIM + colh + e + 1];
                float v0 = alpha * (acc[mi][ni][half * 2 + 0] + bkd * sv0 + skd * bv0 + 4096.0f * bkd * bv0);
                float v1 = alpha * (acc[mi][ni][half * 2 + 1] + bkd * sv1 + skd * bv1 + 4096.0f * bkd * bv1);
                *reinterpret_cast<uint32_t*>(Cg + d * D_DIM + e) =
                    (uint32_t)__half_as_ushort(__float2half_rn(v0)) |
                    ((uint32_t)__half_as_ushort(__float2half_rn(v1)) << 16);
            }
        }
}

// ---------------- PB build (unchanged) ---------------------------------------
#define AT_STAGE 16384
#define AT_SMEM  (3 * AT_STAGE)

__device__ __forceinline__ void load_tile128(uint32_t sdst, const f16* __restrict__ g,
                                             int row0, int col0, int ld) {
    const int t = threadIdx.x;
    #pragma unroll
    for (int i = 0; i < 2; i++) {
        int idx = t + i * 256;
        int r = idx >> 2, c = idx & 3;
        const f16* src = g + (size_t)(row0 + r) * ld + col0 + c * 8;
        uint32_t off = r * 64 + ((c ^ ((r >> 1) & 3)) << 4);
        cp_async16(sdst + off, src);
    }
}
#define CP_WAIT2()  asm volatile("cp.async.wait_group 2;" ::: "memory")

__global__ __launch_bounds__(256) void k_pb(const f16* __restrict__ wo)
{
    const int bh = blockIdx.z;
    const int b = bh >> 4;
    const int h = bh & 15;
    const int row0 = blockIdx.y * 128;
    const f16* Ah = wo;
    const f16* Bh = g_KVth + ((size_t)bh << 14);
    const int acol = h * 128;
    f16* PBb = g_PB + (size_t)b * E_DIM * E_DIM;

    extern __shared__ __align__(1024) char smdyn[];
    const uint32_t sbase = smem_u32(smdyn);
    const int tid = threadIdx.x;
    const int wid = tid >> 5, lane = tid & 31;
    const int wm = (wid & 1) * 64;
    const int wn = (wid >> 1) * 32;

    uint32_t aoff[4][2];
    #pragma unroll
    for (int mi = 0; mi < 4; mi++) {
        int r = wm + mi * 16 + (lane & 15);
        #pragma unroll
        for (int ks = 0; ks < 2; ks++) {
            int kc = ks * 2 + (lane >> 4);
            aoff[mi][ks] = r * 64 + ((kc ^ ((r >> 1) & 3)) << 4);
        }
    }
    uint32_t boff[2][2];
    #pragma unroll
    for (int p = 0; p < 2; p++) {
        int g2 = lane >> 3;
        int r = wn + p * 16 + ((g2 >> 1) << 3) + (lane & 7);
        #pragma unroll
        for (int ks = 0; ks < 2; ks++) {
            int kc = ks * 2 + (g2 & 1);
            boff[p][ks] = r * 64 + ((kc ^ ((r >> 1) & 3)) << 4);
        }
    }

    float acc[4][4][4];
    #pragma unroll
    for (int mi = 0; mi < 4; mi++)
        #pragma unroll
        for (int ni = 0; ni < 4; ni++)
            #pragma unroll
            for (int qq = 0; qq < 4; qq++) acc[mi][ni][qq] = 0.0f;

    #pragma unroll
    for (int i = 0; i < 2; i++) {
        uint32_t sb = sbase + i * AT_STAGE;
        int k0 = i * 32;
        load_tile128(sb + 0,    Ah, row0, acol + k0, E_DIM);
        load_tile128(sb + 8192, Bh, 0, k0, D_DIM);
        CP_COMMIT();
    }

    for (int c = 0; c < 4; c++) {
        if (c + 2 < 4) {
            uint32_t sb = sbase + ((c + 2) % 3) * AT_STAGE;
            int k0 = (c + 2) * 32;
            load_tile128(sb + 0,    Ah, row0, acol + k0, E_DIM);
            load_tile128(sb + 8192, Bh, 0, k0, D_DIM);
        }
        CP_COMMIT();
        CP_WAIT2();
        __syncthreads();

        const uint32_t sb = sbase + (c % 3) * AT_STAGE;
        #pragma unroll
        for (int ks = 0; ks < 2; ks++) {
            uint32_t ah[4][4], bh[4][2];
            #pragma unroll
            for (int mi = 0; mi < 4; mi++)
                ldsm4(ah[mi], sb + aoff[mi][ks]);
            #pragma unroll
            for (int p = 0; p < 2; p++) {
                uint32_t t4[4];
                ldsm4(t4, sb + 8192 + boff[p][ks]);
                bh[2 * p][0] = t4[0]; bh[2 * p][1] = t4[1];
                bh[2 * p + 1][0] = t4[2]; bh[2 * p + 1][1] = t4[3];
            }
            #pragma unroll
            for (int mi = 0; mi < 4; mi++)
                #pragma unroll
                for (int ni = 0; ni < 4; ni++)
                    mma_f16(acc[mi][ni], ah[mi], bh[ni]);
        }
        __syncthreads();
    }

    const int lg = lane >> 2;
    const int lc2 = (lane & 3) * 2;
    #pragma unroll
    for (int mi = 0; mi < 4; mi++) {
        #pragma unroll
        for (int half = 0; half < 2; half++) {
            int row = row0 + wm + mi * 16 + lg + half * 8;
            #pragma unroll
            for (int ni = 0; ni < 4; ni++) {
                int col = h * 128 + wn + ni * 8 + lc2;
                *reinterpret_cast<uint32_t*>(PBb + (size_t)row * E_DIM + col) =
                    (uint32_t)__half_as_ushort(__float2half_rn(acc[mi][ni][half * 2 + 0])) |
                    ((uint32_t)__half_as_ushort(__float2half_rn(acc[mi][ni][half * 2 + 1])) << 16);
            }
        }
    }
}

// fbias[b][n] = bo[n] + sum_k bq[k] * PB[b][n][k]
__global__ __launch_bounds__(256) void k_fbias(const float* __restrict__ bq,
                                               const float* __restrict__ bo)
{
    int gw = (blockIdx.x * 256 + threadIdx.x) >> 5;
    int lane = threadIdx.x & 31;
    int b = gw >> 11;
    int n = gw & 2047;
    const f16* row = g_PB + ((size_t)b * E_DIM + n) * E_DIM;
    float s = 0.0f;
    for (int k = lane; k < E_DIM; k += 32)
        s += __half2float(row[k]) * bq[k];
    #pragma unroll
    for (int o = 16; o > 0; o >>= 1) s += __shfl_xor_sync(0xFFFFFFFFu, s, o);
    if (lane == 0) g_fbias[b * E_DIM + n] = s + bo[n];
}

// column sums of x (per batch): sx[b][e] = sum_t xh[b,t,e]
__global__ __launch_bounds__(256) void k_colsum()
{
    const int b = blockIdx.y;
    const int e = blockIdx.x * 256 + threadIdx.x;
    const f16* base = g_xh + ((size_t)b * T_DIM) * E_DIM + e;
    float s = 0.0f;
    for (int t = 0; t < T_DIM; t++)
        s += __half2float(base[(size_t)t * E_DIM]);
    g_sx[b * E_DIM + e] = s;
}

// sxwk[b][n] = Wk[n,:]·sx[b];  sxwv[b][n] = Wv[n,:]·sx[b]   (warp per (b,m,n))
__global__ __launch_bounds__(256) void k_sxw()
{
    int gw = (blockIdx.x * 256 + threadIdx.x) >> 5;
    int lane = threadIdx.x & 31;
    int b = gw >> 12;
    int m = (gw >> 11) & 1;
    int n = gw & 2047;
    const f16* row = g_Wh[m ? 2 : 1] + (size_t)n * E_DIM;
    const float* sx = g_sx + b * E_DIM;
    float s = 0.0f;
    for (int k = lane; k < E_DIM; k += 32)
        s += __half2float(row[k]) * sx[k];
    #pragma unroll
    for (int o = 16; o > 0; o >>= 1) s += __shfl_xor_sync(0xFFFFFFFFu, s, o);
    if (lane == 0) {
        if (m) g_sxwv[b * E_DIM + n] = s;
        else   g_sxwk[b * E_DIM + n] = s;
    }
}

// fused fp32 -> fp16 conversion: x then 4 weight matrices
__global__ __launch_bounds__(256) void k_split_all(
    const float* __restrict__ x,
    const float* __restrict__ Wq, const float* __restrict__ Wk,
    const float* __restrict__ Wv, const float* __restrict__ Wo,
    f16* __restrict__ xh, f16* __restrict__ whBase)
{
    const size_t WSZ4 = (size_t)E_DIM * E_DIM / 4;
    const size_t NX4  = (size_t)BT_DIM * E_DIM / 4;
    size_t i4 = (size_t)blockIdx.x * 256 + threadIdx.x;
    const float* src;
    f16* dst;
    if (i4 < NX4) {
        src = x; dst = xh;
    } else {
        size_t r = i4 - NX4;
        int w = (int)(r / WSZ4);
        i4 = r - (size_t)w * WSZ4;
        src = (w == 0) ? Wq : (w == 1) ? Wk : (w == 2) ? Wv : Wo;
        dst = whBase + (size_t)w * E_DIM * E_DIM;
    }
    float4 v = *reinterpret_cast<const float4*>(src + i4 * 4);
    uint32_t hw0 = (uint32_t)__half_as_ushort(__float2half_rn(v.x)) |
                   ((uint32_t)__half_as_ushort(__float2half_rn(v.y)) << 16);
    uint32_t hw1 = (uint32_t)__half_as_ushort(__float2half_rn(v.z)) |
                   ((uint32_t)__half_as_ushort(__float2half_rn(v.w)) << 16);
    *reinterpret_cast<uint2*>(dst + i4 * 4) = make_uint2(hw0, hw1);
}

// ---------------- launch -----------------------------------------------------
extern "C" void kernel_launch(void* const* d_in, const int* in_sizes, int n_in,
                              void* d_out, int out_size)
{
    const float* x  = (const float*)d_in[0];
    const float* Wq = (const float*)d_in[1];
    const float* bq = (const float*)d_in[2];
    const float* Wk = (const float*)d_in[3];
    const float* bk = (const float*)d_in[4];
    const float* Wv = (const float*)d_in[5];
    const float* bv = (const float*)d_in[6];
    const float* Wo = (const float*)d_in[7];
    const float* bo = (const float*)d_in[8];
    float* out = (float*)d_out;

    f16 *xh, *wh, *Gp, *Zp, *PBp, *Mp;
    cudaGetSymbolAddress((void**)&xh, g_xh);
    cudaGetSymbolAddress((void**)&wh, g_Wh);
    cudaGetSymbolAddress((void**)&Gp, g_G);
    cudaGetSymbolAddress((void**)&Zp, g_Z);
    cudaGetSymbolAddress((void**)&PBp, g_PB);
    cudaGetSymbolAddress((void**)&Mp, g_M);

    cudaFuncSetAttribute(k_out,  cudaFuncAttributeMaxDynamicSharedMemorySize, PG_SMEM);
    cudaFuncSetAttribute(k_ABt,  cudaFuncAttributeMaxDynamicSharedMemorySize, PG_SMEM);
    cudaFuncSetAttribute(k_gram, cudaFuncAttributeMaxDynamicSharedMemorySize, GR_SMEM);
    cudaFuncSetAttribute(k_kvh,  cudaFuncAttributeMaxDynamicSharedMemorySize, KH_SMEM);
    cudaFuncSetAttribute(k_pb,   cudaFuncAttributeMaxDynamicSharedMemorySize, AT_SMEM);

    const size_t WSZ = (size_t)E_DIM * E_DIM;
    const size_t total4 = ((size_t)BT_DIM * E_DIM + 4 * WSZ) / 4;

    k_split_all<<<(int)(total4 / 256), 256>>>(x, Wq, Wk, Wv, Wo, xh, wh);

    k_colsum<<<dim3(E_DIM / 256, B_DIM), 256>>>();
    k_gram<<<dim3(E_DIM / 256, E_DIM / 128, B_DIM), 256, GR_SMEM>>>();
    k_sxw<<<(B_DIM * 2 * E_DIM * 32) / 256, 256>>>();

    // Z = Wv @ G[b]
    k_ABt<<<dim3(E_DIM / 256, E_DIM / 128, B_DIM), 256, PG_SMEM>>>(
        wh + 2 * WSZ, 0, Gp, WSZ, Zp, WSZ);

    k_kvh<<<64, 256, KH_SMEM>>>(bk, bv);

    k_pb<<<dim3(1, E_DIM / 128, 64), 256, AT_SMEM>>>(wh + 3 * WSZ);

    // M = PB[b] @ Wq
    k_ABt<<<dim3(E_DIM / 256, E_DIM / 128, B_DIM), 256, PG_SMEM>>>(
        PBp, WSZ, wh + 0 * WSZ, 0, Mp, WSZ);
    k_fbias<<<(B_DIM * E_DIM * 32) / 256, 256>>>(bq, bo);

    k_out<<<dim3(E_DIM / 256, BT_DIM / 128), 256, PG_SMEM>>>(out);
}

// round 13
// speedup vs baseline: 1.0671x; 1.0671x over previous
#include <cuda_runtime.h>
#include <cuda_fp16.h>
#include <cstdint>

#define B_DIM 4
#define T_DIM 4096
#define E_DIM 2048
#define H_DIM 16
#define D_DIM 128
#define BT_DIM 16384
#define KVSPLIT 4

typedef __half f16;

// ---------------- scratch (device globals; no allocations allowed) ----------
__device__ f16 g_xh[(size_t)BT_DIM * E_DIM];
__device__ f16 g_Wh[4][(size_t)E_DIM * E_DIM];
__device__ f16 g_Kh[(size_t)BT_DIM * E_DIM];
__device__ f16 g_Vh[(size_t)BT_DIM * E_DIM];
__device__ f16 g_PB[(size_t)B_DIM * E_DIM * E_DIM];  // per-batch KV*Wo^T  [n][k]
__device__ f16 g_M[(size_t)B_DIM * E_DIM * E_DIM];   // Mt[b][n][j] = PB Wq
__device__ float g_fbias[B_DIM * E_DIM];
__device__ float g_KVp[(size_t)KVSPLIT * 64 * D_DIM * D_DIM];
__device__ f16 g_KVth[64 * D_DIM * D_DIM];           // [bh][d][e], alpha-folded

// ---------------- helpers ----------------------------------------------------
__device__ __forceinline__ uint32_t smem_u32(const void* p) {
    uint32_t a;
    asm("{ .reg .u64 t; cvta.to.shared.u64 t, %1; cvt.u32.u64 %0, t; }" : "=r"(a) : "l"(p));
    return a;
}
__device__ __forceinline__ void cp_async16(uint32_t sdst, const void* gsrc) {
    asm volatile("cp.async.cg.shared.global [%0], [%1], 16;" :: "r"(sdst), "l"(gsrc) : "memory");
}
#define CP_COMMIT() asm volatile("cp.async.commit_group;" ::: "memory")
#define CP_WAIT1()  asm volatile("cp.async.wait_group 1;" ::: "memory")
#define CP_WAIT2()  asm volatile("cp.async.wait_group 2;" ::: "memory")

__device__ __forceinline__ void ldsm4(uint32_t* r, uint32_t a) {
    asm volatile("ldmatrix.sync.aligned.m8n8.x4.shared.b16 {%0,%1,%2,%3}, [%4];"
                 : "=r"(r[0]), "=r"(r[1]), "=r"(r[2]), "=r"(r[3]) : "r"(a));
}
__device__ __forceinline__ void ldsm4t(uint32_t* r, uint32_t a) {
    asm volatile("ldmatrix.sync.aligned.m8n8.x4.trans.shared.b16 {%0,%1,%2,%3}, [%4];"
                 : "=r"(r[0]), "=r"(r[1]), "=r"(r[2]), "=r"(r[3]) : "r"(a));
}
__device__ __forceinline__ void mma_f16(float* c, const uint32_t* a, const uint32_t* b) {
    asm volatile(
        "mma.sync.aligned.m16n8k16.row.col.f32.f16.f16.f32 "
        "{%0,%1,%2,%3}, {%4,%5,%6,%7}, {%8,%9}, {%0,%1,%2,%3};"
        : "+f"(c[0]), "+f"(c[1]), "+f"(c[2]), "+f"(c[3])
        : "r"(a[0]), "r"(a[1]), "r"(a[2]), "r"(a[3]), "r"(b[0]), "r"(b[1]));
}

// 128B-row tile loader (64 f16/row), swizzle chunk c^(r&7)
__device__ __forceinline__ void load_rows64(uint32_t sdst, const f16* __restrict__ g,
                                            int row0, int col0, int ld, int iters) {
    const int t = threadIdx.x;
    #pragma unroll 8
    for (int i = 0; i < iters; i++) {
        int idx = t + i * 256;
        int r = idx >> 3, c = idx & 7;
        const f16* src = g + (size_t)(row0 + r) * ld + col0 + c * 8;
        cp_async16(sdst + r * 128 + ((c ^ (r & 7)) << 4), src);
    }
}
// 512B-row tile: 64 rows x 256 f16 (32 chunks)
__device__ __forceinline__ void load_tile512B(uint32_t sdst, const f16* __restrict__ g,
                                              int row0, int col0, int ld) {
    const int t = threadIdx.x;
    #pragma unroll
    for (int i = 0; i < 8; i++) {
        int idx = t + i * 256;
        int r = idx >> 5, cc = idx & 31;
        const f16* src = g + (size_t)(row0 + r) * ld + col0 + cc * 8;
        cp_async16(sdst + r * 512 + ((cc ^ (r & 7)) << 4), src);
    }
}

// ---------------- big GEMM core: CTA 128x256, warp 64x64, BK=128, 2 stages ---
#define PG_A0 0
#define PG_A1 16384
#define PG_B0 32768
#define PG_B1 65536
#define PG_STAGE 98304
#define PG_SMEM  (2 * PG_STAGE)

__device__ __forceinline__ void gemm_128x256_core(
    const f16* __restrict__ Ah, const f16* __restrict__ Bh,
    const float* __restrict__ bias, bool out_f32,
    float* __restrict__ Cf, f16* __restrict__ C1)
{
    extern __shared__ __align__(1024) char smdyn[];
    const uint32_t sbase = smem_u32(smdyn);
    const int tid = threadIdx.x;
    const int wid = tid >> 5, lane = tid & 31;
    const int wm = (wid & 1) * 64;
    const int wn = (wid >> 1) * 64;
    const int row0 = blockIdx.y * 128;
    const int n0 = blockIdx.x * 256;

    uint32_t abase[4];
    #pragma unroll
    for (int mi = 0; mi < 4; mi++) {
        int r = wm + mi * 16 + (lane & 15);
        int hi = lane >> 4;
        abase[mi] = r * 128 + ((hi ^ (r & 7)) << 4);
    }
    uint32_t bbase[4];
    #pragma unroll
    for (int p = 0; p < 4; p++) {
        int g2 = lane >> 3;
        int r = wn + p * 16 + ((g2 >> 1) << 3) + (lane & 7);
        bbase[p] = r * 128 + (((g2 & 1) ^ (r & 7)) << 4);
    }

    float acc[4][8][4];
    #pragma unroll
    for (int mi = 0; mi < 4; mi++)
        #pragma unroll
        for (int ni = 0; ni < 8; ni++)
            #pragma unroll
            for (int q = 0; q < 4; q++) acc[mi][ni][q] = 0.0f;

    #pragma unroll
    for (int i = 0; i < 2; i++) {
        uint32_t sb = sbase + i * PG_STAGE;
        int k0 = i * 128;
        load_rows64(sb + PG_A0, Ah, row0, k0,      E_DIM, 4);
        load_rows64(sb + PG_A1, Ah, row0, k0 + 64, E_DIM, 4);
        load_rows64(sb + PG_B0, Bh, n0,   k0,      E_DIM, 8);
        load_rows64(sb + PG_B1, Bh, n0,   k0 + 64, E_DIM, 8);
        CP_COMMIT();
    }

    const int NC = E_DIM / 128;
    for (int c = 0; c < NC; c++) {
        CP_WAIT1();
        __syncthreads();
        const uint32_t sb = sbase + (c & 1) * PG_STAGE;
        #pragma unroll
        for (int ks = 0; ks < 8; ks++) {
            const uint32_t asub = sb + ((ks & 4) ? PG_A1 : PG_A0);
            const uint32_t bsub = sb + ((ks & 4) ? PG_B1 : PG_B0);
            const uint32_t kx = (ks & 3) << 5;
            uint32_t ah[4][4], bh[8][2];
            #pragma unroll
            for (int mi = 0; mi < 4; mi++)
                ldsm4(ah[mi], asub + (abase[mi] ^ kx));
            #pragma unroll
            for (int p = 0; p < 4; p++) {
                uint32_t t4[4];
                ldsm4(t4, bsub + (bbase[p] ^ kx));
                bh[2 * p][0] = t4[0]; bh[2 * p][1] = t4[1];
                bh[2 * p + 1][0] = t4[2]; bh[2 * p + 1][1] = t4[3];
            }
            #pragma unroll
            for (int mi = 0; mi < 4; mi++)
                #pragma unroll
                for (int ni = 0; ni < 8; ni++)
                    mma_f16(acc[mi][ni], ah[mi], bh[ni]);
        }
        __syncthreads();
        if (c + 2 < NC) {
            uint32_t sb2 = sbase + (c & 1) * PG_STAGE;
            int k0 = (c + 2) * 128;
            load_rows64(sb2 + PG_A0, Ah, row0, k0,      E_DIM, 4);
            load_rows64(sb2 + PG_A1, Ah, row0, k0 + 64, E_DIM, 4);
            load_rows64(sb2 + PG_B0, Bh, n0,   k0,      E_DIM, 8);
            load_rows64(sb2 + PG_B1, Bh, n0,   k0 + 64, E_DIM, 8);
        }
        CP_COMMIT();
    }

    const int lg = lane >> 2;
    const int lc2 = (lane & 3) * 2;
    #pragma unroll
    for (int mi = 0; mi < 4; mi++) {
        #pragma unroll
        for (int half = 0; half < 2; half++) {
            int row = row0 + wm + mi * 16 + lg + half * 8;
            #pragma unroll
            for (int ni = 0; ni < 8; ni++) {
                int col = n0 + wn + ni * 8 + lc2;
                float v0 = acc[mi][ni][half * 2 + 0] + bias[col];
                float v1 = acc[mi][ni][half * 2 + 1] + bias[col + 1];
                if (out_f32) {
                    *reinterpret_cast<float2*>(Cf + (size_t)row * E_DIM + col) = make_float2(v0, v1);
                } else {
                    *reinterpret_cast<uint32_t*>(C1 + (size_t)row * E_DIM + col) =
                        (uint32_t)__half_as_ushort(__float2half_rn(v0)) |
                        ((uint32_t)__half_as_ushort(__float2half_rn(v1)) << 16);
                }
            }
        }
    }
}

// fused K/V projections: grid (8, 128, 2)
__global__ __launch_bounds__(256, 1) void k_kv(
    const f16* __restrict__ xh, const f16* __restrict__ whBase,
    const float* __restrict__ bk, const float* __restrict__ bv)
{
    const int z = blockIdx.z;
    const size_t WSZ = (size_t)E_DIM * E_DIM;
    const f16* Bh = whBase + (size_t)(z + 1) * WSZ;
    const float* bias = (z == 0) ? bk : bv;
    f16* C1 = (z == 0) ? g_Kh : g_Vh;
    gemm_128x256_core(xh, Bh, bias, false, nullptr, C1);
}

// final output: OUT = x @ Mt[b]^T + fbias[b]   (grid (8, 128))
__global__ __launch_bounds__(256, 1) void k_out(float* __restrict__ out)
{
    const int b = blockIdx.y >> 5;
    gemm_128x256_core(g_xh, g_M + (size_t)b * E_DIM * E_DIM,
                      g_fbias + b * E_DIM, true, out, nullptr);
}

// ---------------- M build: Mt[b][n][j] = sum_k PB[b][n][k] * Wq[k][j] --------
__global__ __launch_bounds__(256, 1) void k_mbuild(const f16* __restrict__ wq)
{
    extern __shared__ __align__(1024) char smdyn[];
    const uint32_t sbase = smem_u32(smdyn);
    const int tid = threadIdx.x;
    const int wid = tid >> 5, lane = tid & 31;
    const int wm = (wid & 1) * 64;
    const int wn = (wid >> 1) * 64;
    const int b = blockIdx.z;
    const int row0 = blockIdx.y * 128;
    const int j0 = blockIdx.x * 256;
    const f16* Ah = g_PB + (size_t)b * E_DIM * E_DIM;
    f16* Mout = g_M + (size_t)b * E_DIM * E_DIM;
    const int q = lane >> 3;

    uint32_t abase[4];
    #pragma unroll
    for (int mi = 0; mi < 4; mi++) {
        int r = wm + mi * 16 + (lane & 15);
        int hi = lane >> 4;
        abase[mi] = r * 128 + ((hi ^ (r & 7)) << 4);
    }
    uint32_t btbase[4];
    #pragma unroll
    for (int p = 0; p < 4; p++) {
        int r0 = ((q & 1) << 3) + (lane & 7);
        int cc = ((wn + p * 16) >> 3) + (q >> 1);
        btbase[p] = r0 * 512 + ((cc ^ (r0 & 7)) << 4);
    }

    float acc[4][8][4];
    #pragma unroll
    for (int mi = 0; mi < 4; mi++)
        #pragma unroll
        for (int ni = 0; ni < 8; ni++)
            #pragma unroll
            for (int qq = 0; qq < 4; qq++) acc[mi][ni][qq] = 0.0f;

    #pragma unroll
    for (int i = 0; i < 2; i++) {
        uint32_t sb = sbase + i * PG_STAGE;
        int k0 = i * 128;
        load_rows64(sb + PG_A0, Ah, row0, k0,      E_DIM, 4);
        load_rows64(sb + PG_A1, Ah, row0, k0 + 64, E_DIM, 4);
        load_tile512B(sb + PG_B0, wq, k0,      j0, E_DIM);
        load_tile512B(sb + PG_B1, wq, k0 + 64, j0, E_DIM);
        CP_COMMIT();
    }

    const int NC = E_DIM / 128;
    for (int c = 0; c < NC; c++) {
        CP_WAIT1();
        __syncthreads();
        const uint32_t sb = sbase + (c & 1) * PG_STAGE;
        #pragma unroll
        for (int ks = 0; ks < 8; ks++) {
            const uint32_t asub = sb + ((ks & 4) ? PG_A1 : PG_A0);
            const uint32_t bsub = sb + ((ks & 4) ? PG_B1 : PG_B0);
            const uint32_t kx = (ks & 3) << 5;
            const uint32_t kofs = (uint32_t)(ks & 3) * 8192;
            uint32_t ah[4][4], bh[8][2];
            #pragma unroll
            for (int mi = 0; mi < 4; mi++)
                ldsm4(ah[mi], asub + (abase[mi] ^ kx));
            #pragma unroll
            for (int p = 0; p < 4; p++) {
                uint32_t t4[4];
                ldsm4t(t4, bsub + btbase[p] + kofs);
                bh[2 * p][0] = t4[0]; bh[2 * p][1] = t4[1];
                bh[2 * p + 1][0] = t4[2]; bh[2 * p + 1][1] = t4[3];
            }
            #pragma unroll
            for (int mi = 0; mi < 4; mi++)
                #pragma unroll
                for (int ni = 0; ni < 8; ni++)
                    mma_f16(acc[mi][ni], ah[mi], bh[ni]);
        }
        __syncthreads();
        if (c + 2 < NC) {
            uint32_t sb2 = sbase + (c & 1) * PG_STAGE;
            int k0 = (c + 2) * 128;
            load_rows64(sb2 + PG_A0, Ah, row0, k0,      E_DIM, 4);
            load_rows64(sb2 + PG_A1, Ah, row0, k0 + 64, E_DIM, 4);
            load_tile512B(sb2 + PG_B0, wq, k0,      j0, E_DIM);
            load_tile512B(sb2 + PG_B1, wq, k0 + 64, j0, E_DIM);
        }
        CP_COMMIT();
    }

    const int lg = lane >> 2;
    const int lc2 = (lane & 3) * 2;
    #pragma unroll
    for (int mi = 0; mi < 4; mi++) {
        #pragma unroll
        for (int half = 0; half < 2; half++) {
            int row = row0 + wm + mi * 16 + lg + half * 8;
            #pragma unroll
            for (int ni = 0; ni < 8; ni++) {
                int col = j0 + wn + ni * 8 + lc2;
                *reinterpret_cast<uint32_t*>(Mout + (size_t)row * E_DIM + col) =
                    (uint32_t)__half_as_ushort(__float2half_rn(acc[mi][ni][half * 2 + 0])) |
                    ((uint32_t)__half_as_ushort(__float2half_rn(acc[mi][ni][half * 2 + 1])) << 16);
            }
        }
    }
}

// fbias[b][n] = bo[n] + sum_k bq[k] * PB[b][n][k]
__global__ __launch_bounds__(256) void k_fbias(const float* __restrict__ bq,
                                               const float* __restrict__ bo)
{
    int gw = (blockIdx.x * 256 + threadIdx.x) >> 5;
    int lane = threadIdx.x & 31;
    int b = gw >> 11;
    int n = gw & 2047;
    const f16* row = g_PB + ((size_t)b * E_DIM + n) * E_DIM;
    float s = 0.0f;
    for (int k = lane; k < E_DIM; k += 32)
        s += __half2float(row[k]) * bq[k];
    #pragma unroll
    for (int o = 16; o > 0; o >>= 1) s += __shfl_xor_sync(0xFFFFFFFFu, s, o);
    if (lane == 0) g_fbias[b * E_DIM + n] = s + bo[n];
}

// ---------------- KV gemm ----------------------------------------------------
#define KV_A 0
#define KV_B 16384
#define KV_STAGE 32768
#define KV_SMEM  (2 * KV_STAGE)

__device__ __forceinline__ void load_kv_tile(uint32_t sdst, const f16* __restrict__ g,
                                             int btrow0, int colh)
{
    const int t = threadIdx.x;
    #pragma unroll
    for (int i = 0; i < 4; i++) {
        int idx = t + i * 256;
        int r = idx >> 4, cc = idx & 15;
        const f16* src = g + (size_t)(btrow0 + r) * E_DIM + colh + cc * 8;
        cp_async16(sdst + r * 256 + ((cc ^ (r & 7)) << 4), src);
    }
}

__global__ __launch_bounds__(256, 1) void k_kv_mma()
{
    const int split = blockIdx.x;
    const int bh = blockIdx.z;
    const int b = bh >> 4;
    const int h = bh & 15;
    const int colh = h * 128;
    const int bt_begin = b * T_DIM + split * (T_DIM / KVSPLIT);

    extern __shared__ __align__(1024) char smdyn[];
    const uint32_t sbase = smem_u32(smdyn);
    const int tid = threadIdx.x;
    const int wid = tid >> 5, lane = tid & 31;
    const int wm = (wid & 1) * 64;
    const int wn = (wid >> 1) * 32;
    const int q = lane >> 3;

    uint32_t abase[4];
    #pragma unroll
    for (int mi = 0; mi < 4; mi++) {
        int r0 = ((q & 2) << 2) + (lane & 7);
        int cc = ((wm + mi * 16) >> 3) + (q & 1);
        abase[mi] = r0 * 256 + ((cc ^ (r0 & 7)) << 4);
    }
    uint32_t bbase[2];
    #pragma unroll
    for (int p = 0; p < 2; p++) {
        int r0 = ((q & 1) << 3) + (lane & 7);
        int cc = ((wn + p * 16) >> 3) + (q >> 1);
        bbase[p] = r0 * 256 + ((cc ^ (r0 & 7)) << 4);
    }

    float acc[4][4][4];
    #pragma unroll
    for (int mi = 0; mi < 4; mi++)
        #pragma unroll
        for (int ni = 0; ni < 4; ni++)
            #pragma unroll
            for (int qq = 0; qq < 4; qq++) acc[mi][ni][qq] = 0.0f;

    #pragma unroll
    for (int i = 0; i < 2; i++) {
        uint32_t sb = sbase + i * KV_STAGE;
        load_kv_tile(sb + KV_A, g_Kh, bt_begin + i * 64, colh);
        load_kv_tile(sb + KV_B, g_Vh, bt_begin + i * 64, colh);
        CP_COMMIT();
    }

    const int NC = (T_DIM / KVSPLIT) / 64;   // 16
    for (int c = 0; c < NC; c++) {
        CP_WAIT1();
        __syncthreads();
        const uint32_t sb = sbase + (c & 1) * KV_STAGE;
        #pragma unroll
        for (int ks = 0; ks < 4; ks++) {
            const uint32_t kofs = ks * 4096;
            uint32_t ah[4][4], bh[4][2];
            #pragma unroll
            for (int mi = 0; mi < 4; mi++)
                ldsm4t(ah[mi], sb + KV_A + abase[mi] + kofs);
            #pragma unroll
            for (int p = 0; p < 2; p++) {
                uint32_t t4[4];
                ldsm4t(t4, sb + KV_B + bbase[p] + kofs);
                bh[2 * p][0] = t4[0]; bh[2 * p][1] = t4[1];
                bh[2 * p + 1][0] = t4[2]; bh[2 * p + 1][1] = t4[3];
            }
            #pragma unroll
            for (int mi = 0; mi < 4; mi++)
                #pragma unroll
                for (int ni = 0; ni < 4; ni++)
                    mma_f16(acc[mi][ni], ah[mi], bh[ni]);
        }
        __syncthreads();
        if (c + 2 < NC) {
            uint32_t sb2 = sbase + (c & 1) * KV_STAGE;
            load_kv_tile(sb2 + KV_A, g_Kh, bt_begin + (c + 2) * 64, colh);
            load_kv_tile(sb2 + KV_B, g_Vh, bt_begin + (c + 2) * 64, colh);
        }
        CP_COMMIT();
    }

    float* Cg = g_KVp + ((size_t)(split * 64 + bh) << 14);
    const int lg = lane >> 2;
    const int lc2 = (lane & 3) * 2;
    #pragma unroll
    for (int mi = 0; mi < 4; mi++)
        #pragma unroll
        for (int half = 0; half < 2; half++) {
            int row = wm + mi * 16 + lg + half * 8;   // d
            #pragma unroll
            for (int ni = 0; ni < 4; ni++) {
                int col = wn + ni * 8 + lc2;          // e
                *reinterpret_cast<float2*>(Cg + row * D_DIM + col) =
                    make_float2(acc[mi][ni][half * 2 + 0], acc[mi][ni][half * 2 + 1]);
            }
        }
}

__global__ __launch_bounds__(256) void k_kvreduce()
{
    const float alpha = 0.08838834764831845f;
    int idx = blockIdx.x * 256 + threadIdx.x;
    float sv = 0.0f;
    #pragma unroll
    for (int p = 0; p < KVSPLIT; p++) sv += g_KVp[((size_t)p << 20) + idx];
    g_KVth[idx] = __float2half_rn(alpha * sv);
}

// ---------------- PB build ---------------------------------------------------
#define AT_STAGE 16384
#define AT_SMEM  (3 * AT_STAGE)

__device__ __forceinline__ void load_tile128(uint32_t sdst, const f16* __restrict__ g,
                                             int row0, int col0, int ld) {
    const int t = threadIdx.x;
    #pragma unroll
    for (int i = 0; i < 2; i++) {
        int idx = t + i * 256;
        int r = idx >> 2, c = idx & 3;
        const f16* src = g + (size_t)(row0 + r) * ld + col0 + c * 8;
        uint32_t off = r * 64 + ((c ^ ((r >> 1) & 3)) << 4);
        cp_async16(sdst + off, src);
    }
}

__global__ __launch_bounds__(256) void k_pb(const f16* __restrict__ wo)
{
    const int bh = blockIdx.z;
    const int b = bh >> 4;
    const int h = bh & 15;
    const int row0 = blockIdx.y * 128;
    const f16* Ah = wo;
    const f16* Bh = g_KVth + ((size_t)bh << 14);
    const int acol = h * 128;
    f16* PBb = g_PB + (size_t)b * E_DIM * E_DIM;

    extern __shared__ __align__(1024) char smdyn[];
    const uint32_t sbase = smem_u32(smdyn);
    const int tid = threadIdx.x;
    const int wid = tid >> 5, lane = tid & 31;
    const int wm = (wid & 1) * 64;
    const int wn = (wid >> 1) * 32;

    uint32_t aoff[4][2];
    #pragma unroll
    for (int mi = 0; mi < 4; mi++) {
        int r = wm + mi * 16 + (lane & 15);
        #pragma unroll
        for (int ks = 0; ks < 2; ks++) {
            int kc = ks * 2 + (lane >> 4);
            aoff[mi][ks] = r * 64 + ((kc ^ ((r >> 1) & 3)) << 4);
        }
    }
    uint32_t boff[2][2];
    #pragma unroll
    for (int p = 0; p < 2; p++) {
        int g2 = lane >> 3;
        int r = wn + p * 16 + ((g2 >> 1) << 3) + (lane & 7);
        #pragma unroll
        for (int ks = 0; ks < 2; ks++) {
            int kc = ks * 2 + (g2 & 1);
            boff[p][ks] = r * 64 + ((kc ^ ((r >> 1) & 3)) << 4);
        }
    }

    float acc[4][4][4];
    #pragma unroll
    for (int mi = 0; mi < 4; mi++)
        #pragma unroll
        for (int ni = 0; ni < 4; ni++)
            #pragma unroll
            for (int qq = 0; qq < 4; qq++) acc[mi][ni][qq] = 0.0f;

    #pragma unroll
    for (int i = 0; i < 2; i++) {
        uint32_t sb = sbase + i * AT_STAGE;
        int k0 = i * 32;
        load_tile128(sb + 0,    Ah, row0, acol + k0, E_DIM);
        load_tile128(sb + 8192, Bh, 0, k0, D_DIM);
        CP_COMMIT();
    }

    for (int c = 0; c < 4; c++) {
        if (c + 2 < 4) {
            uint32_t sb = sbase + ((c + 2) % 3) * AT_STAGE;
            int k0 = (c + 2) * 32;
            load_tile128(sb + 0,    Ah, row0, acol + k0, E_DIM);
            load_tile128(sb + 8192, Bh, 0, k0, D_DIM);
        }
        CP_COMMIT();
        CP_WAIT2();
        __syncthreads();

        const uint32_t sb = sbase + (c % 3) * AT_STAGE;
        #pragma unroll
        for (int ks = 0; ks < 2; ks++) {
            uint32_t ah[4][4], bh[4][2];
            #pragma unroll
            for (int mi = 0; mi < 4; mi++)
                ldsm4(ah[mi], sb + aoff[mi][ks]);
            #pragma unroll
            for (int p = 0; p < 2; p++) {
                uint32_t t4[4];
                ldsm4(t4, sb + 8192 + boff[p][ks]);
                bh[2 * p][0] = t4[0]; bh[2 * p][1] = t4[1];
                bh[2 * p + 1][0] = t4[2]; bh[2 * p + 1][1] = t4[3];
            }
            #pragma unroll
            for (int mi = 0; mi < 4; mi++)
                #pragma unroll
                for (int ni = 0; ni < 4; ni++)
                    mma_f16(acc[mi][ni], ah[mi], bh[ni]);
        }
        __syncthreads();
    }

    const int lg = lane >> 2;
    const int lc2 = (lane & 3) * 2;
    #pragma unroll
    for (int mi = 0; mi < 4; mi++) {
        #pragma unroll
        for (int half = 0; half < 2; half++) {
            int row = row0 + wm + mi * 16 + lg + half * 8;
            #pragma unroll
            for (int ni = 0; ni < 4; ni++) {
                int col = h * 128 + wn + ni * 8 + lc2;
                *reinterpret_cast<uint32_t*>(PBb + (size_t)row * E_DIM + col) =
                    (uint32_t)__half_as_ushort(__float2half_rn(acc[mi][ni][half * 2 + 0])) |
                    ((uint32_t)__half_as_ushort(__float2half_rn(acc[mi][ni][half * 2 + 1])) << 16);
            }
        }
    }
}

// fused fp32 -> fp16 conversion: x then 4 weight matrices; 16 floats/thread
__global__ __launch_bounds__(256) void k_split_all(
    const float* __restrict__ x,
    const float* __restrict__ Wq, const float* __restrict__ Wk,
    const float* __restrict__ Wv, const float* __restrict__ Wo,
    f16* __restrict__ xh, f16* __restrict__ whBase)
{
    const size_t WSZ16 = (size_t)E_DIM * E_DIM / 16;
    const size_t NX16  = (size_t)BT_DIM * E_DIM / 16;
    size_t i16 = (size_t)blockIdx.x * 256 + threadIdx.x;
    const float* src;
    f16* dst;
    if (i16 < NX16) {
        src = x; dst = xh;
    } else {
        size_t r = i16 - NX16;
        int w = (int)(r / WSZ16);
        i16 = r - (size_t)w * WSZ16;
        src = (w == 0) ? Wq : (w == 1) ? Wk : (w == 2) ? Wv : Wo;
        dst = whBase + (size_t)w * E_DIM * E_DIM;
    }
    const float4* s4 = reinterpret_cast<const float4*>(src + i16 * 16);
    float4 v[4];
    #pragma unroll
    for (int j = 0; j < 4; j++) v[j] = s4[j];
    uint4 o[2];
    #pragma unroll
    for (int j = 0; j < 2; j++) {
        float4 a = v[j * 2], b2 = v[j * 2 + 1];
        o[j].x = (uint32_t)__half_as_ushort(__float2half_rn(a.x)) |
                 ((uint32_t)__half_as_ushort(__float2half_rn(a.y)) << 16);
        o[j].y = (uint32_t)__half_as_ushort(__float2half_rn(a.z)) |
                 ((uint32_t)__half_as_ushort(__float2half_rn(a.w)) << 16);
        o[j].z = (uint32_t)__half_as_ushort(__float2half_rn(b2.x)) |
                 ((uint32_t)__half_as_ushort(__float2half_rn(b2.y)) << 16);
        o[j].w = (uint32_t)__half_as_ushort(__float2half_rn(b2.z)) |
                 ((uint32_t)__half_as_ushort(__float2half_rn(b2.w)) << 16);
    }
    uint4* d4 = reinterpret_cast<uint4*>(dst + i16 * 16);
    d4[0] = o[0];
    d4[1] = o[1];
}

// ---------------- launch -----------------------------------------------------
extern "C" void kernel_launch(void* const* d_in, const int* in_sizes, int n_in,
                              void* d_out, int out_size)
{
    const float* x  = (const float*)d_in[0];
    const float* Wq = (const float*)d_in[1];
    const float* bq = (const float*)d_in[2];
    const float* Wk = (const float*)d_in[3];
    const float* bk = (const float*)d_in[4];
    const float* Wv = (const float*)d_in[5];
    const float* bv = (const float*)d_in[6];
    const float* Wo = (const float*)d_in[7];
    const float* bo = (const float*)d_in[8];
    float* out = (float*)d_out;

    f16 *xh, *wh;
    cudaGetSymbolAddress((void**)&xh, g_xh);
    cudaGetSymbolAddress((void**)&wh, g_Wh);

    cudaFuncSetAttribute(k_kv,     cudaFuncAttributeMaxDynamicSharedMemorySize, PG_SMEM);
    cudaFuncSetAttribute(k_out,    cudaFuncAttributeMaxDynamicSharedMemorySize, PG_SMEM);
    cudaFuncSetAttribute(k_mbuild, cudaFuncAttributeMaxDynamicSharedMemorySize, PG_SMEM);
    cudaFuncSetAttribute(k_kv_mma, cudaFuncAttributeMaxDynamicSharedMemorySize, KV_SMEM);
    cudaFuncSetAttribute(k_pb,     cudaFuncAttributeMaxDynamicSharedMemorySize, AT_SMEM);

    const size_t WSZ = (size_t)E_DIM * E_DIM;
    const size_t total16 = ((size_t)BT_DIM * E_DIM + 4 * WSZ) / 16;

    k_split_all<<<(int)(total16 / 256), 256>>>(x, Wq, Wk, Wv, Wo, xh, wh);

    k_kv<<<dim3(E_DIM / 256, BT_DIM / 128, 2), 256, PG_SMEM>>>(xh, wh, bk, bv);

    k_kv_mma<<<dim3(KVSPLIT, 1, 64), 256, KV_SMEM>>>();
    k_kvreduce<<<(64 * D_DIM * D_DIM) / 256, 256>>>();

    k_pb<<<dim3(1, E_DIM / 128, 64), 256, AT_SMEM>>>(wh + 3 * WSZ);

    k_mbuild<<<dim3(E_DIM / 256, E_DIM / 128, B_DIM), 256, PG_SMEM>>>(wh + 0 * WSZ);
    k_fbias<<<(B_DIM * E_DIM * 32) / 256, 256>>>(bq, bo);

    k_out<<<dim3(E_DIM / 256, BT_DIM / 128), 256, PG_SMEM>>>(out);
}